// round 11
// baseline (speedup 1.0000x reference)
#include <cuda_runtime.h>
#include <cuda_device_runtime_api.h>

// Problem dims (fixed by the dataset)
constexpr int L = 13;
constexpr int B = 16;
constexpr int S = 512;
constexpr int D = 768;
constexpr int W = 256;
constexpr int D4 = D / 4;          // 192 float4 per row

// Scratch: starts[b][w] = first s with seg[b,s] >= w; starts[b][W] = S.
__device__ int g_starts[B * (W + 1)];

// Kernel A: one block per sentence. Stage the 2KB seg row into smem with one
// coalesced parallel load, then 257 threads binary-search smem. Fires the
// PDL trigger as soon as its stores are issued so kernel B can ramp up.
__global__ void __launch_bounds__(S) compute_starts_kernel(const int* __restrict__ seg) {
    __shared__ int s_seg[S];
    const int b = blockIdx.x;
    s_seg[threadIdx.x] = seg[b * S + threadIdx.x];
    __syncthreads();

    int w = threadIdx.x;
    if (w <= W) {
        int lo = 0, hi = S;
        while (lo < hi) {
            int mid = (lo + hi) >> 1;
            if (s_seg[mid] < w) lo = mid + 1; else hi = mid;
        }
        g_starts[b * (W + 1) + w] = lo;
    }
    // Allow the dependent kernel to begin launching; memory visibility is
    // enforced by cudaGridDependencySynchronize() on the consumer side.
    cudaTriggerProgrammaticLaunchCompletion();
}

// Kernel B: proven-best streaming body (78us, DRAM ~75% = mixed R/W ceiling).
// One thread per output float4; warps never cross rows (192 % 32 == 0).
// Prolog (index math) overlaps kernel A via PDL; sync before reading spans.
__global__ void __launch_bounds__(256) segment_sum_kernel(
    const float4* __restrict__ hidden,   // [L,B,S,D4]
    float4* __restrict__ out             // [L,B,W,D4]
) {
    int idx = blockIdx.x * blockDim.x + threadIdx.x;   // output float4 index
    int d4 = idx % D4;
    int w_lin = idx / D4;          // l*B*W + b*W + w
    int w = w_lin % W;
    int bl = w_lin / W;            // l*B + b
    int b = bl % B;

    // Wait for kernel A's writes to be visible.
    cudaGridDependencySynchronize();

    int s0 = g_starts[b * (W + 1) + w];
    int s1 = g_starts[b * (W + 1) + w + 1];

    const float4* src = hidden + ((long long)bl * S + s0) * D4 + d4;
    float4 acc = make_float4(0.f, 0.f, 0.f, 0.f);
    for (int s = s0; s < s1; ++s) {
        float4 v = *src;
        acc.x += v.x; acc.y += v.y; acc.z += v.z; acc.w += v.w;
        src += D4;
    }
    out[idx] = acc;
}

extern "C" void kernel_launch(void* const* d_in, const int* in_sizes, int n_in,
                              void* d_out, int out_size) {
    const float* hidden = (const float*)d_in[0];
    const int*   seg    = (const int*)d_in[1];
    // d_in[2] = num_words scalar — W hardcoded.

    compute_starts_kernel<<<B, S>>>(seg);

    long long total = (long long)L * B * W * D4;   // 10,223,616
    int threads = 256;
    int blocks = (int)(total / threads);           // 39936 exactly

    // Launch kernel B with Programmatic Dependent Launch so its setup
    // overlaps kernel A's execution.
    cudaLaunchConfig_t cfg = {};
    cfg.gridDim  = dim3((unsigned)blocks, 1, 1);
    cfg.blockDim = dim3((unsigned)threads, 1, 1);
    cfg.dynamicSmemBytes = 0;
    cfg.stream = 0;
    cudaLaunchAttribute attr[1];
    attr[0].id = cudaLaunchAttributeProgrammaticStreamSerialization;
    attr[0].val.programmaticStreamSerializationAllowed = 1;
    cfg.attrs = attr;
    cfg.numAttrs = 1;

    cudaLaunchKernelEx(&cfg, segment_sum_kernel,
                       (const float4*)hidden, (float4*)d_out);
}